// round 13
// baseline (speedup 1.0000x reference)
#include <cuda_runtime.h>
#include <cuda_fp16.h>
#include <cstdint>
#include <climits>

#define N_NODES 50000
#define N_EDGES 800000
#define IN_DIM 128
#define HID 64
#define N_LAYERS 3
#define SCB 512
#define NSB ((N_NODES + SCB - 1) / SCB)

#define NT_W (N_EDGES / 32)          // 25000 warp-tiles, exact
#define EMMA_BLOCKS 740              // 5 blocks/SM x 148
#define TW_TOT (EMMA_BLOCKS * 4)

// ---- dynamic SMEM layout for k_edgemma (40KB, no static shared) ----
#define SM_U    0        // 4 warps x 8KB stripe: U fp16 4KB (union zbuf 32x64 f32 = 8KB)
#define SM_WHI  32768    // W2 fp16 [k][n] swizzled, 8KB
#define SMEM_DYN 40960

// ---------------- scratch ----------------
__device__ float g_h[N_NODES * HID];
__device__ float g_A[N_NODES * HID];
__device__ float g_Q[N_NODES * HID];
__device__ unsigned g_z[N_NODES * HID];     // ordered-encoded max accumulator
__device__ int   g_counts[N_NODES];
__device__ int   g_offsets[N_NODES + 1];
__device__ int   g_cursor[N_NODES];
__device__ int   g_csr[N_EDGES];
__device__ int   g_csr_dst[N_EDGES];
__device__ int   g_bsum[128];
__device__ int   g_bbase[128];
__device__ int   g_is64;
__device__ unsigned g_W2t[N_LAYERS * 64 * 32];   // [L][k][n2] fp16x2

// ---------------- helpers ----------------
__device__ __forceinline__ unsigned long long pk2(float x, float y) {
    unsigned long long r;
    asm("mov.b64 %0, {%1, %2};" : "=l"(r) : "f"(x), "f"(y));
    return r;
}
__device__ __forceinline__ unsigned long long pkdup(float x) {
    unsigned long long r;
    asm("mov.b64 %0, {%1, %1};" : "=l"(r) : "f"(x));
    return r;
}
__device__ __forceinline__ float2 upk2(unsigned long long v) {
    float2 r;
    asm("mov.b64 {%0, %1}, %2;" : "=f"(r.x), "=f"(r.y) : "l"(v));
    return r;
}
__device__ __forceinline__ unsigned long long ffma2(unsigned long long a,
                                                    unsigned long long b,
                                                    unsigned long long c) {
    unsigned long long d;
    asm("fma.rn.f32x2 %0, %1, %2, %3;" : "=l"(d) : "l"(a), "l"(b), "l"(c));
    return d;
}
__device__ __forceinline__ uint32_t smem_u32(const void* p) {
    uint32_t a;
    asm("{ .reg .u64 t; cvta.to.shared.u64 t, %1; cvt.u32.u64 %0, t; }" : "=r"(a) : "l"(p));
    return a;
}
__device__ __forceinline__ unsigned encf(float f) {
    unsigned u = __float_as_uint(f);
    return (u & 0x80000000u) ? ~u : (u | 0x80000000u);
}
__device__ __forceinline__ float decf(unsigned u) {
    return (u & 0x80000000u) ? __uint_as_float(u & 0x7FFFFFFFu) : __uint_as_float(~u);
}

// ---- warp-MMA primitives (base-target legal: sm_80+) ----
__device__ __forceinline__ void ldsm4(uint32_t* r, uint32_t a) {
    asm volatile("ldmatrix.sync.aligned.m8n8.x4.shared.b16 {%0,%1,%2,%3}, [%4];"
        : "=r"(r[0]), "=r"(r[1]), "=r"(r[2]), "=r"(r[3]) : "r"(a));
}
__device__ __forceinline__ void ldsm4t(uint32_t* r, uint32_t a) {
    asm volatile("ldmatrix.sync.aligned.m8n8.x4.trans.shared.b16 {%0,%1,%2,%3}, [%4];"
        : "=r"(r[0]), "=r"(r[1]), "=r"(r[2]), "=r"(r[3]) : "r"(a));
}
__device__ __forceinline__ void mma16816h(float* d, const uint32_t* a, uint32_t b0, uint32_t b1) {
    asm volatile("mma.sync.aligned.m16n8k16.row.col.f32.f16.f16.f32 "
        "{%0,%1,%2,%3}, {%4,%5,%6,%7}, {%8,%9}, {%0,%1,%2,%3};"
        : "+f"(d[0]), "+f"(d[1]), "+f"(d[2]), "+f"(d[3])
        : "r"(a[0]), "r"(a[1]), "r"(a[2]), "r"(a[3]), "r"(b0), "r"(b1));
}

// ---------------- CSR build ----------------
__global__ void k_zero(const int* __restrict__ ei32) {
    int i = blockIdx.x * blockDim.x + threadIdx.x;
    if (i < N_NODES) g_counts[i] = 0;
    if (blockIdx.x == 0 && threadIdx.x == 0) {
        int z = 0;
#pragma unroll
        for (int j = 1; j < 16; j += 2) z |= ei32[j];
        g_is64 = (z == 0) ? 1 : 0;
    }
}
__device__ __forceinline__ int edge_val(const int* __restrict__ e, int i, int is64) {
    return is64 ? e[2 * i] : e[i];
}
__global__ void k_hist(const int* __restrict__ ei32) {
    int e = blockIdx.x * blockDim.x + threadIdx.x;
    if (e < N_EDGES) {
        int d = edge_val(ei32, N_EDGES + e, g_is64);
        if ((unsigned)d < (unsigned)N_NODES) atomicAdd(&g_counts[d], 1);
    }
}
__device__ __forceinline__ int warp_incl_scan(int v, int lane) {
#pragma unroll
    for (int o = 1; o < 32; o <<= 1) {
        int t = __shfl_up_sync(0xffffffffu, v, o);
        if (lane >= o) v += t;
    }
    return v;
}
__global__ void __launch_bounds__(SCB) k_scan1() {
    __shared__ int ws[SCB / 32];
    int tid = threadIdx.x, lane = tid & 31, wid = tid >> 5;
    int i = blockIdx.x * SCB + tid;
    int v = (i < N_NODES) ? g_counts[i] : 0;
#pragma unroll
    for (int o = 16; o; o >>= 1) v += __shfl_xor_sync(0xffffffffu, v, o);
    if (lane == 0) ws[wid] = v;
    __syncthreads();
    if (wid == 0) {
        int s = (lane < SCB / 32) ? ws[lane] : 0;
#pragma unroll
        for (int o = 16; o; o >>= 1) s += __shfl_xor_sync(0xffffffffu, s, o);
        if (lane == 0) g_bsum[blockIdx.x] = s;
    }
}
__global__ void __launch_bounds__(128) k_scan2() {
    __shared__ int wsum[4];
    int tid = threadIdx.x, lane = tid & 31, wid = tid >> 5;
    int c = (tid < NSB) ? g_bsum[tid] : 0;
    int v = warp_incl_scan(c, lane);
    if (lane == 31) wsum[wid] = v;
    __syncthreads();
    int base = 0;
    for (int j = 0; j < wid; j++) base += wsum[j];
    v += base;
    if (tid < NSB) g_bbase[tid] = v - c;
    if (tid == NSB - 1) g_offsets[N_NODES] = v;
}
__global__ void __launch_bounds__(SCB) k_scan3() {
    __shared__ int wsum[SCB / 32];
    int tid = threadIdx.x, lane = tid & 31, wid = tid >> 5;
    int i = blockIdx.x * SCB + tid;
    int c = (i < N_NODES) ? g_counts[i] : 0;
    int v = warp_incl_scan(c, lane);
    if (lane == 31) wsum[wid] = v;
    __syncthreads();
    int base = g_bbase[blockIdx.x];
    for (int j = 0; j < wid; j++) base += wsum[j];
    int excl = base + v - c;
    if (i < N_NODES) {
        g_offsets[i] = excl;
        g_cursor[i]  = excl;
    }
}
__global__ void k_scatter(const int* __restrict__ ei32) {
    int e = blockIdx.x * blockDim.x + threadIdx.x;
    if (e < N_EDGES) {
        int is64 = g_is64;
        int d = edge_val(ei32, N_EDGES + e, is64);
        int s = edge_val(ei32, e, is64);
        if ((unsigned)d < (unsigned)N_NODES && (unsigned)s < (unsigned)N_NODES) {
            int pos = atomicAdd(&g_cursor[d], 1);
            g_csr[pos] = s;
            g_csr_dst[pos] = d;
        }
    }
}

// ---------------- W2 fp16 precompute: [L][k][n2] ----------------
__global__ void k_w2cvt(const float* __restrict__ W2) {
    int i = blockIdx.x * blockDim.x + threadIdx.x;
    if (i >= N_LAYERS * 64 * 32) return;
    int L = i / 2048, rem = i % 2048;
    int k = rem >> 5, n2 = rem & 31;
    const float* WL = W2 + L * HID * HID;
    __half2 hb = __floats2half2_rn(WL[k * HID + 2 * n2], WL[k * HID + 2 * n2 + 1]);
    g_W2t[i] = *reinterpret_cast<unsigned*>(&hb);
}

__global__ void k_zinit() {
    int i = blockIdx.x * blockDim.x + threadIdx.x;
    if (i < N_NODES * HID) g_z[i] = 0u;
}

// ---------------- input projection ----------------
__global__ void __launch_bounds__(256) k_proj(const float* __restrict__ x,
                                              const float* __restrict__ Wp,
                                              const float* __restrict__ bp) {
    __shared__ unsigned long long Wsp[IN_DIM * 32];
    __shared__ float xs[32][IN_DIM];
    int tid = threadIdx.x;
    for (int i = tid; i < IN_DIM * 32; i += 256) {
        int k = i >> 5, lc = i & 31;
        Wsp[i] = pk2(Wp[k * HID + 2 * lc], Wp[k * HID + 2 * lc + 1]);
    }
    int w = tid >> 5, l = tid & 31;
    int m0 = w * 4;
#pragma unroll
    for (int sub = 0; sub < 4; sub++) {
        int n = blockIdx.x * 32 + m0 + sub;
        if (n < N_NODES)
            ((float4*)xs[m0 + sub])[l] = ((const float4*)(x + (long)n * IN_DIM))[l];
    }
    __syncthreads();
    unsigned long long bv = pk2(bp[2 * l], bp[2 * l + 1]);
    unsigned long long acc[4] = {bv, bv, bv, bv};
#pragma unroll 4
    for (int k = 0; k < IN_DIM; k++) {
        unsigned long long wv = Wsp[k * 32 + l];
#pragma unroll
        for (int sub = 0; sub < 4; sub++)
            acc[sub] = ffma2(pkdup(xs[m0 + sub][k]), wv, acc[sub]);
    }
#pragma unroll
    for (int sub = 0; sub < 4; sub++) {
        int n = blockIdx.x * 32 + m0 + sub;
        if (n < N_NODES)
            *(float2*)(g_h + (long)n * HID + 2 * l) = upk2(acc[sub]);
    }
}

// ---------------- node GEMMs (fused with previous-layer finish) ----------
__global__ void __launch_bounds__(256) k_AQ(const float* __restrict__ W1,
                                            const float* __restrict__ b1,
                                            const float* __restrict__ b2prev,
                                            int do_fin) {
    __shared__ unsigned long long Wsa[HID * 32];
    __shared__ unsigned long long Wsb[HID * 32];
    __shared__ float hs[32][HID];
    int tid = threadIdx.x;
    for (int i = tid; i < HID * 32; i += 256) {
        int k = i >> 5, lc = i & 31;
        Wsa[i] = pk2(W1[k * HID + 2 * lc], W1[k * HID + 2 * lc + 1]);
        Wsb[i] = pk2(W1[(HID + k) * HID + 2 * lc], W1[(HID + k) * HID + 2 * lc + 1]);
    }
    int w = tid >> 5, l = tid & 31;
    int m0 = w * 4;
#pragma unroll
    for (int sub = 0; sub < 4; sub++) {
        int n = blockIdx.x * 32 + m0 + sub;
        if (n >= N_NODES) continue;
        float2 h2 = *(const float2*)(g_h + (long)n * HID + 2 * l);
        if (do_fin) {
            int deg = g_offsets[n + 1] - g_offsets[n];
            if (deg > 0) {
                unsigned e0 = g_z[(long)n * HID + 2 * l];
                unsigned e1 = g_z[(long)n * HID + 2 * l + 1];
                float2 b2v = *(const float2*)(b2prev + 2 * l);
                h2.x = fmaxf(decf(e0) + b2v.x, 0.f) + h2.x;
                h2.y = fmaxf(decf(e1) + b2v.y, 0.f) + h2.y;
                *(uint2*)(g_z + (long)n * HID + 2 * l) = make_uint2(0u, 0u);
            }
            *(float2*)(g_h + (long)n * HID + 2 * l) = h2;
        }
        ((float2*)hs[m0 + sub])[l] = h2;
    }
    __syncthreads();
    unsigned long long accA[4] = {0ull, 0ull, 0ull, 0ull};
    unsigned long long accQ[4] = {0ull, 0ull, 0ull, 0ull};
#pragma unroll 4
    for (int k = 0; k < HID; k++) {
        unsigned long long wa = Wsa[k * 32 + l];
        unsigned long long wb = Wsb[k * 32 + l];
#pragma unroll
        for (int sub = 0; sub < 4; sub++) {
            unsigned long long hk2 = pkdup(hs[m0 + sub][k]);
            accA[sub] = ffma2(hk2, wa, accA[sub]);
            accQ[sub] = ffma2(hk2, wb, accQ[sub]);
        }
    }
    float2 bv = *(const float2*)(b1 + 2 * l);
#pragma unroll
    for (int sub = 0; sub < 4; sub++) {
        int n = blockIdx.x * 32 + m0 + sub;
        if (n >= N_NODES) continue;
        float2 fA = upk2(accA[sub]);
        float2 fQ = upk2(accQ[sub]);
        float2 A;
        A.x = fA.x - fQ.x + bv.x;
        A.y = fA.y - fQ.y + bv.y;
        *(float2*)(g_A + (long)n * HID + 2 * l) = A;
        *(float2*)(g_Q + (long)n * HID + 2 * l) = fQ;
    }
}

// ---------------- HMMA edge phase ----------------
// Contiguous chunk of 32-edge tiles per warp. U = relu(A[dst]+Q[src]) fp16,
// single-term MMA (U*W fp16), segmented max; interior segments plain-stored,
// chunk-boundary segments via encoded atomicMax.
__device__ __forceinline__ void flushmax(int node, int l, float m0, float m1, bool boundary) {
    unsigned* p = g_z + (long)node * HID + 2 * l;
    unsigned e0 = encf(m0), e1 = encf(m1);
    if (boundary) {
        atomicMax(p, e0);
        atomicMax(p + 1, e1);
    } else {
        *(uint2*)p = make_uint2(e0, e1);
    }
}

__global__ void __launch_bounds__(128, 5) k_edgemma(int layer) {
    extern __shared__ char sm[];
    uint32_t smb = smem_u32(sm);
    int tid = threadIdx.x, w = tid >> 5, l = tid & 31;

    const unsigned* wh = g_W2t + layer * 2048;
    for (int i = tid; i < 2048; i += 128) {
        int k = i >> 5, n2 = i & 31;
        uint32_t off = (uint32_t)(k * 128 + ((n2 * 4) ^ ((k & 7) << 4)));
        *(unsigned*)(sm + SM_WHI + off) = wh[i];
    }
    __syncthreads();

    char* uw = sm + SM_U + w * 8192;         // U fp16 4KB (zbuf 8KB union)
    uint32_t uw32 = smb + SM_U + w * 8192;
    float* zb = (float*)uw;

    int lrow = l & 7;
    int arow = ((l >> 3) & 1) * 8 + lrow;
    int kgrp = l >> 4;
    uint32_t a_base0 = uw32 + arow * 128;
    uint32_t w_hi_base = smb + SM_WHI + arow * 128;

    int wg = blockIdx.x * 4 + w;
    int c0 = (int)((long)NT_W * wg / TW_TOT);
    int c1 = (int)((long)NT_W * (wg + 1) / TW_TOT);
    if (c0 >= c1) return;

    int mysrc = g_csr[c0 * 32 + l];
    int mydst = g_csr_dst[c0 * 32 + l];

    float m0 = -INFINITY, m1 = -INFINITY;
    int prev = INT_MIN;
    bool at_start = true;
    int prev_dst_stage = -1;
    float2 a2 = make_float2(0.f, 0.f);

    for (int t = c0; t < c1; t++) {
        // ---- stage 32 edges (fp16), unrolled for LDG batching ----
#pragma unroll 8
        for (int rr = 0; rr < 32; rr++) {
            int src = __shfl_sync(0xffffffffu, mysrc, rr);
            int dst = __shfl_sync(0xffffffffu, mydst, rr);
            if (dst != prev_dst_stage) {
                a2 = *(const float2*)(g_A + (long)dst * HID + 2 * l);
                prev_dst_stage = dst;
            }
            float2 q2 = *(const float2*)(g_Q + (long)src * HID + 2 * l);
            float u0 = fmaxf(a2.x + q2.x, 0.f);
            float u1 = fmaxf(a2.y + q2.y, 0.f);
            __half2 hb = __floats2half2_rn(u0, u1);
            uint32_t off = (uint32_t)(rr * 128 + ((l * 4) ^ ((rr & 7) << 4)));
            *(unsigned*)(uw + off) = *reinterpret_cast<unsigned*>(&hb);
        }
        __syncwarp();

        // prefetch next tile's indices
        int nsrc = 0, ndst = 0;
        if (t + 1 < c1) {
            nsrc = g_csr[(t + 1) * 32 + l];
            ndst = g_csr_dst[(t + 1) * 32 + l];
        }

        // ---- MMA: single fp16 term ----
        float d[2][8][4];
#pragma unroll
        for (int rb = 0; rb < 2; rb++)
#pragma unroll
            for (int nb = 0; nb < 8; nb++)
#pragma unroll
                for (int j = 0; j < 4; j++) d[rb][nb][j] = 0.f;

#pragma unroll
        for (int ks = 0; ks < 4; ks++) {
            uint32_t axor = (uint32_t)(((ks * 2 + kgrp) ^ lrow) << 4);
            uint32_t ah[2][4];
            ldsm4(ah[0], a_base0 + axor);
            ldsm4(ah[1], a_base0 + 2048 + axor);
#pragma unroll
            for (int np = 0; np < 4; np++) {
                uint32_t bxor = (uint32_t)(((np * 2 + kgrp) ^ lrow) << 4);
                uint32_t bh[4];
                ldsm4t(bh, w_hi_base + ks * 2048 + bxor);
#pragma unroll
                for (int rb = 0; rb < 2; rb++) {
                    mma16816h(d[rb][2 * np],     ah[rb], bh[0], bh[1]);
                    mma16816h(d[rb][2 * np + 1], ah[rb], bh[2], bh[3]);
                }
            }
        }
        __syncwarp();

        // ---- D -> zbuf (swizzled) ----
#pragma unroll
        for (int rb = 0; rb < 2; rb++) {
#pragma unroll
            for (int nb = 0; nb < 8; nb++) {
                int c0w = nb * 8 + (l & 3) * 2;
                int r0 = rb * 16 + (l >> 2);
                int r1 = r0 + 8;
                *(float2*)&zb[r0 * 64 + (c0w ^ ((r0 & 7) << 3))] =
                    make_float2(d[rb][nb][0], d[rb][nb][1]);
                *(float2*)&zb[r1 * 64 + (c0w ^ ((r1 & 7) << 3))] =
                    make_float2(d[rb][nb][2], d[rb][nb][3]);
            }
        }
        __syncwarp();

        // ---- segmented max; interior plain-store, boundaries atomic ----
        for (int rr = 0; rr < 32; rr++) {
            int dcur = __shfl_sync(0xffffffffu, mydst, rr);
            if (dcur != prev) {
                if (prev != INT_MIN) {
                    flushmax(prev, l, m0, m1, at_start);
                    at_start = false;
                }
                m0 = -INFINITY; m1 = -INFINITY;
                prev = dcur;
            }
            float2 zv = *(const float2*)&zb[rr * 64 + ((2 * l) ^ ((rr & 7) << 3))];
            m0 = fmaxf(m0, zv.x);
            m1 = fmaxf(m1, zv.y);
        }
        __syncwarp();
        mysrc = nsrc;
        mydst = ndst;
    }
    if (prev != INT_MIN) flushmax(prev, l, m0, m1, true);   // chunk-end: boundary
}

// ---------------- last-layer finish: out = (relu(max+b2)+h) @ Wo + bo ----------------
__global__ void __launch_bounds__(256) k_finlast(const float* __restrict__ b2,
                                                 const float* __restrict__ Wo,
                                                 const float* __restrict__ bo,
                                                 float* __restrict__ out) {
    int w = threadIdx.x >> 5, l = threadIdx.x & 31;
    int n = blockIdx.x * 8 + w;
    if (n >= N_NODES) return;
    int deg = g_offsets[n + 1] - g_offsets[n];
    float2 r = *(const float2*)(g_h + (long)n * HID + 2 * l);
    if (deg > 0) {
        unsigned e0 = g_z[(long)n * HID + 2 * l];
        unsigned e1 = g_z[(long)n * HID + 2 * l + 1];
        float2 b2v = *(const float2*)(b2 + 2 * l);
        r.x = fmaxf(decf(e0) + b2v.x, 0.f) + r.x;
        r.y = fmaxf(decf(e1) + b2v.y, 0.f) + r.y;
    }
    float2 wo = *(const float2*)(Wo + 2 * l);
    float s = fmaf(r.x, wo.x, r.y * wo.y);
#pragma unroll
    for (int o = 16; o; o >>= 1) s += __shfl_xor_sync(0xffffffffu, s, o);
    if (l == 0) out[n] = s + bo[0];
}

// ---------------- launch ----------------
extern "C" void kernel_launch(void* const* d_in, const int* in_sizes, int n_in,
                              void* d_out, int out_size) {
    const float* x  = (const float*)d_in[0];
    const int*   ei = (const int*)d_in[1];
    const float* Wp = (const float*)d_in[2];
    const float* bp = (const float*)d_in[3];
    const float* W1 = (const float*)d_in[4];
    const float* b1 = (const float*)d_in[5];
    const float* W2 = (const float*)d_in[6];
    const float* b2 = (const float*)d_in[7];
    const float* Wo = (const float*)d_in[8];
    const float* bo = (const float*)d_in[9];
    float* out = (float*)d_out;

    k_zero<<<(N_NODES + 255) / 256, 256>>>(ei);
    k_hist<<<(N_EDGES + 255) / 256, 256>>>(ei);
    k_scan1<<<NSB, SCB>>>();
    k_scan2<<<1, 128>>>();
    k_scan3<<<NSB, SCB>>>();
    k_scatter<<<(N_EDGES + 255) / 256, 256>>>(ei);

    k_w2cvt<<<(N_LAYERS * 64 * 32 + 255) / 256, 256>>>(W2);
    k_zinit<<<(N_NODES * HID + 1023) / 1024, 1024>>>();

    const int NB = (N_NODES + 31) / 32;
    k_proj<<<NB, 256>>>(x, Wp, bp);
    for (int L = 0; L < N_LAYERS; L++) {
        k_AQ<<<NB, 256>>>(W1 + (long)L * 2 * HID * HID, b1 + (long)L * HID,
                          (L > 0) ? (b2 + (long)(L - 1) * HID) : b2, L > 0);
        k_edgemma<<<EMMA_BLOCKS, 128, SMEM_DYN>>>(L);
    }
    k_finlast<<<(N_NODES + 7) / 8, 256>>>(b2 + (long)(N_LAYERS - 1) * HID, Wo, bo, out);
}

// round 14
// speedup vs baseline: 1.0244x; 1.0244x over previous
#include <cuda_runtime.h>
#include <cuda_fp16.h>
#include <cstdint>
#include <climits>

#define N_NODES 50000
#define N_EDGES 800000
#define IN_DIM 128
#define HID 64
#define N_LAYERS 3
#define SCB 512
#define NSB ((N_NODES + SCB - 1) / SCB)

#define NT_W (N_EDGES / 32)          // 25000 warp-tiles, exact
#define EMMA_BLOCKS 592              // 4 blocks/SM x 148
#define TW_TOT (EMMA_BLOCKS * 4)

// ---- dynamic SMEM layout for k_edgemma (40KB, no static shared) ----
#define SM_U    0        // 4 warps x 8KB stripe: U fp16 4KB (union zbuf 32x64 f32 = 8KB)
#define SM_WHI  32768    // W2 fp16 [k][n] swizzled, 8KB
#define SMEM_DYN 40960

// ---------------- scratch ----------------
__device__ float g_h[N_NODES * HID];
__device__ float g_A[N_NODES * HID];
__device__ float g_Q[N_NODES * HID];
__device__ unsigned g_z[N_NODES * HID];     // ordered-encoded max accumulator
__device__ int   g_counts[N_NODES];
__device__ int   g_offsets[N_NODES + 1];
__device__ int   g_cursor[N_NODES];
__device__ int   g_csr[N_EDGES];
__device__ int   g_csr_dst[N_EDGES];
__device__ int   g_bsum[128];
__device__ int   g_bbase[128];
__device__ int   g_is64;
__device__ unsigned g_W2t[N_LAYERS * 64 * 32];   // [L][k][n2] fp16x2

// ---------------- helpers ----------------
__device__ __forceinline__ unsigned long long pk2(float x, float y) {
    unsigned long long r;
    asm("mov.b64 %0, {%1, %2};" : "=l"(r) : "f"(x), "f"(y));
    return r;
}
__device__ __forceinline__ unsigned long long pkdup(float x) {
    unsigned long long r;
    asm("mov.b64 %0, {%1, %1};" : "=l"(r) : "f"(x));
    return r;
}
__device__ __forceinline__ float2 upk2(unsigned long long v) {
    float2 r;
    asm("mov.b64 {%0, %1}, %2;" : "=f"(r.x), "=f"(r.y) : "l"(v));
    return r;
}
__device__ __forceinline__ unsigned long long ffma2(unsigned long long a,
                                                    unsigned long long b,
                                                    unsigned long long c) {
    unsigned long long d;
    asm("fma.rn.f32x2 %0, %1, %2, %3;" : "=l"(d) : "l"(a), "l"(b), "l"(c));
    return d;
}
__device__ __forceinline__ uint32_t smem_u32(const void* p) {
    uint32_t a;
    asm("{ .reg .u64 t; cvta.to.shared.u64 t, %1; cvt.u32.u64 %0, t; }" : "=r"(a) : "l"(p));
    return a;
}
__device__ __forceinline__ unsigned encf(float f) {
    unsigned u = __float_as_uint(f);
    return (u & 0x80000000u) ? ~u : (u | 0x80000000u);
}
__device__ __forceinline__ float decf(unsigned u) {
    return (u & 0x80000000u) ? __uint_as_float(u & 0x7FFFFFFFu) : __uint_as_float(~u);
}

// ---- warp-MMA primitives (base-target legal: sm_80+) ----
__device__ __forceinline__ void ldsm4(uint32_t* r, uint32_t a) {
    asm volatile("ldmatrix.sync.aligned.m8n8.x4.shared.b16 {%0,%1,%2,%3}, [%4];"
        : "=r"(r[0]), "=r"(r[1]), "=r"(r[2]), "=r"(r[3]) : "r"(a));
}
__device__ __forceinline__ void ldsm4t(uint32_t* r, uint32_t a) {
    asm volatile("ldmatrix.sync.aligned.m8n8.x4.trans.shared.b16 {%0,%1,%2,%3}, [%4];"
        : "=r"(r[0]), "=r"(r[1]), "=r"(r[2]), "=r"(r[3]) : "r"(a));
}
__device__ __forceinline__ void mma16816h(float* d, const uint32_t* a, uint32_t b0, uint32_t b1) {
    asm volatile("mma.sync.aligned.m16n8k16.row.col.f32.f16.f16.f32 "
        "{%0,%1,%2,%3}, {%4,%5,%6,%7}, {%8,%9}, {%0,%1,%2,%3};"
        : "+f"(d[0]), "+f"(d[1]), "+f"(d[2]), "+f"(d[3])
        : "r"(a[0]), "r"(a[1]), "r"(a[2]), "r"(a[3]), "r"(b0), "r"(b1));
}

// ---------------- init: zero counts+z, convert W2 to fp16, detect dtype ----------------
__global__ void __launch_bounds__(1024) k_init(const int* __restrict__ ei32,
                                               const float* __restrict__ W2) {
    int i = blockIdx.x * blockDim.x + threadIdx.x;
    if (i < N_NODES * HID) g_z[i] = 0u;
    if (i < N_NODES) g_counts[i] = 0;
    if (i < N_LAYERS * 64 * 32) {
        int L = i / 2048, rem = i % 2048;
        int k = rem >> 5, n2 = rem & 31;
        const float* WL = W2 + L * HID * HID;
        __half2 hb = __floats2half2_rn(WL[k * HID + 2 * n2], WL[k * HID + 2 * n2 + 1]);
        g_W2t[i] = *reinterpret_cast<unsigned*>(&hb);
    }
    if (i == 0) {
        int z = 0;
#pragma unroll
        for (int j = 1; j < 16; j += 2) z |= ei32[j];
        g_is64 = (z == 0) ? 1 : 0;
    }
}

__device__ __forceinline__ int edge_val(const int* __restrict__ e, int i, int is64) {
    return is64 ? e[2 * i] : e[i];
}
__global__ void k_hist(const int* __restrict__ ei32) {
    int e = blockIdx.x * blockDim.x + threadIdx.x;
    if (e < N_EDGES) {
        int d = edge_val(ei32, N_EDGES + e, g_is64);
        if ((unsigned)d < (unsigned)N_NODES) atomicAdd(&g_counts[d], 1);
    }
}
__device__ __forceinline__ int warp_incl_scan(int v, int lane) {
#pragma unroll
    for (int o = 1; o < 32; o <<= 1) {
        int t = __shfl_up_sync(0xffffffffu, v, o);
        if (lane >= o) v += t;
    }
    return v;
}
__global__ void __launch_bounds__(SCB) k_scan1() {
    __shared__ int ws[SCB / 32];
    int tid = threadIdx.x, lane = tid & 31, wid = tid >> 5;
    int i = blockIdx.x * SCB + tid;
    int v = (i < N_NODES) ? g_counts[i] : 0;
#pragma unroll
    for (int o = 16; o; o >>= 1) v += __shfl_xor_sync(0xffffffffu, v, o);
    if (lane == 0) ws[wid] = v;
    __syncthreads();
    if (wid == 0) {
        int s = (lane < SCB / 32) ? ws[lane] : 0;
#pragma unroll
        for (int o = 16; o; o >>= 1) s += __shfl_xor_sync(0xffffffffu, s, o);
        if (lane == 0) g_bsum[blockIdx.x] = s;
    }
}
__global__ void __launch_bounds__(128) k_scan2() {
    __shared__ int wsum[4];
    int tid = threadIdx.x, lane = tid & 31, wid = tid >> 5;
    int c = (tid < NSB) ? g_bsum[tid] : 0;
    int v = warp_incl_scan(c, lane);
    if (lane == 31) wsum[wid] = v;
    __syncthreads();
    int base = 0;
    for (int j = 0; j < wid; j++) base += wsum[j];
    v += base;
    if (tid < NSB) g_bbase[tid] = v - c;
    if (tid == NSB - 1) g_offsets[N_NODES] = v;
}
__global__ void __launch_bounds__(SCB) k_scan3() {
    __shared__ int wsum[SCB / 32];
    int tid = threadIdx.x, lane = tid & 31, wid = tid >> 5;
    int i = blockIdx.x * SCB + tid;
    int c = (i < N_NODES) ? g_counts[i] : 0;
    int v = warp_incl_scan(c, lane);
    if (lane == 31) wsum[wid] = v;
    __syncthreads();
    int base = g_bbase[blockIdx.x];
    for (int j = 0; j < wid; j++) base += wsum[j];
    int excl = base + v - c;
    if (i < N_NODES) {
        g_offsets[i] = excl;
        g_cursor[i]  = excl;
    }
}
__global__ void k_scatter(const int* __restrict__ ei32) {
    int e = blockIdx.x * blockDim.x + threadIdx.x;
    if (e < N_EDGES) {
        int is64 = g_is64;
        int d = edge_val(ei32, N_EDGES + e, is64);
        int s = edge_val(ei32, e, is64);
        if ((unsigned)d < (unsigned)N_NODES && (unsigned)s < (unsigned)N_NODES) {
            int pos = atomicAdd(&g_cursor[d], 1);
            g_csr[pos] = s;
            g_csr_dst[pos] = d;
        }
    }
}

// ---------------- input projection ----------------
__global__ void __launch_bounds__(256) k_proj(const float* __restrict__ x,
                                              const float* __restrict__ Wp,
                                              const float* __restrict__ bp) {
    __shared__ unsigned long long Wsp[IN_DIM * 32];
    __shared__ float xs[32][IN_DIM];
    int tid = threadIdx.x;
    for (int i = tid; i < IN_DIM * 32; i += 256) {
        int k = i >> 5, lc = i & 31;
        Wsp[i] = pk2(Wp[k * HID + 2 * lc], Wp[k * HID + 2 * lc + 1]);
    }
    int w = tid >> 5, l = tid & 31;
    int m0 = w * 4;
#pragma unroll
    for (int sub = 0; sub < 4; sub++) {
        int n = blockIdx.x * 32 + m0 + sub;
        if (n < N_NODES)
            ((float4*)xs[m0 + sub])[l] = ((const float4*)(x + (long)n * IN_DIM))[l];
    }
    __syncthreads();
    unsigned long long bv = pk2(bp[2 * l], bp[2 * l + 1]);
    unsigned long long acc[4] = {bv, bv, bv, bv};
#pragma unroll 4
    for (int k = 0; k < IN_DIM; k++) {
        unsigned long long wv = Wsp[k * 32 + l];
#pragma unroll
        for (int sub = 0; sub < 4; sub++)
            acc[sub] = ffma2(pkdup(xs[m0 + sub][k]), wv, acc[sub]);
    }
#pragma unroll
    for (int sub = 0; sub < 4; sub++) {
        int n = blockIdx.x * 32 + m0 + sub;
        if (n < N_NODES)
            *(float2*)(g_h + (long)n * HID + 2 * l) = upk2(acc[sub]);
    }
}

// ---------------- node GEMMs (fused with previous-layer finish) ----------
__global__ void __launch_bounds__(256) k_AQ(const float* __restrict__ W1,
                                            const float* __restrict__ b1,
                                            const float* __restrict__ b2prev,
                                            int do_fin) {
    __shared__ unsigned long long Wsa[HID * 32];
    __shared__ unsigned long long Wsb[HID * 32];
    __shared__ float hs[32][HID];
    int tid = threadIdx.x;
    for (int i = tid; i < HID * 32; i += 256) {
        int k = i >> 5, lc = i & 31;
        Wsa[i] = pk2(W1[k * HID + 2 * lc], W1[k * HID + 2 * lc + 1]);
        Wsb[i] = pk2(W1[(HID + k) * HID + 2 * lc], W1[(HID + k) * HID + 2 * lc + 1]);
    }
    int w = tid >> 5, l = tid & 31;
    int m0 = w * 4;
#pragma unroll
    for (int sub = 0; sub < 4; sub++) {
        int n = blockIdx.x * 32 + m0 + sub;
        if (n >= N_NODES) continue;
        float2 h2 = *(const float2*)(g_h + (long)n * HID + 2 * l);
        if (do_fin) {
            int deg = g_offsets[n + 1] - g_offsets[n];
            if (deg > 0) {
                unsigned e0 = g_z[(long)n * HID + 2 * l];
                unsigned e1 = g_z[(long)n * HID + 2 * l + 1];
                float2 b2v = *(const float2*)(b2prev + 2 * l);
                h2.x = fmaxf(decf(e0) + b2v.x, 0.f) + h2.x;
                h2.y = fmaxf(decf(e1) + b2v.y, 0.f) + h2.y;
                *(uint2*)(g_z + (long)n * HID + 2 * l) = make_uint2(0u, 0u);
            }
            *(float2*)(g_h + (long)n * HID + 2 * l) = h2;
        }
        ((float2*)hs[m0 + sub])[l] = h2;
    }
    __syncthreads();
    unsigned long long accA[4] = {0ull, 0ull, 0ull, 0ull};
    unsigned long long accQ[4] = {0ull, 0ull, 0ull, 0ull};
#pragma unroll 4
    for (int k = 0; k < HID; k++) {
        unsigned long long wa = Wsa[k * 32 + l];
        unsigned long long wb = Wsb[k * 32 + l];
#pragma unroll
        for (int sub = 0; sub < 4; sub++) {
            unsigned long long hk2 = pkdup(hs[m0 + sub][k]);
            accA[sub] = ffma2(hk2, wa, accA[sub]);
            accQ[sub] = ffma2(hk2, wb, accQ[sub]);
        }
    }
    float2 bv = *(const float2*)(b1 + 2 * l);
#pragma unroll
    for (int sub = 0; sub < 4; sub++) {
        int n = blockIdx.x * 32 + m0 + sub;
        if (n >= N_NODES) continue;
        float2 fA = upk2(accA[sub]);
        float2 fQ = upk2(accQ[sub]);
        float2 A;
        A.x = fA.x - fQ.x + bv.x;
        A.y = fA.y - fQ.y + bv.y;
        *(float2*)(g_A + (long)n * HID + 2 * l) = A;
        *(float2*)(g_Q + (long)n * HID + 2 * l) = fQ;
    }
}

// ---------------- HMMA edge phase ----------------
// Contiguous chunk of 32-edge tiles per warp. U = relu(A[dst]+Q[src]) fp16,
// single-term MMA, segmented max; interior segments plain-stored,
// chunk-boundary segments via encoded atomicMax.
__device__ __forceinline__ void flushmax(int node, int l, float m0, float m1, bool boundary) {
    unsigned* p = g_z + (long)node * HID + 2 * l;
    unsigned e0 = encf(m0), e1 = encf(m1);
    if (boundary) {
        atomicMax(p, e0);
        atomicMax(p + 1, e1);
    } else {
        *(uint2*)p = make_uint2(e0, e1);
    }
}

__global__ void __launch_bounds__(128, 4) k_edgemma(int layer) {
    extern __shared__ char sm[];
    uint32_t smb = smem_u32(sm);
    int tid = threadIdx.x, w = tid >> 5, l = tid & 31;

    const unsigned* wh = g_W2t + layer * 2048;
    for (int i = tid; i < 2048; i += 128) {
        int k = i >> 5, n2 = i & 31;
        uint32_t off = (uint32_t)(k * 128 + ((n2 * 4) ^ ((k & 7) << 4)));
        *(unsigned*)(sm + SM_WHI + off) = wh[i];
    }
    __syncthreads();

    char* uw = sm + SM_U + w * 8192;         // U fp16 4KB (zbuf 8KB union)
    uint32_t uw32 = smb + SM_U + w * 8192;
    float* zb = (float*)uw;

    int lrow = l & 7;
    int arow = ((l >> 3) & 1) * 8 + lrow;
    int kgrp = l >> 4;
    uint32_t a_base0 = uw32 + arow * 128;
    uint32_t w_hi_base = smb + SM_WHI + arow * 128;

    int wg = blockIdx.x * 4 + w;
    int c0 = (int)((long)NT_W * wg / TW_TOT);
    int c1 = (int)((long)NT_W * (wg + 1) / TW_TOT);
    if (c0 >= c1) return;

    int mysrc = g_csr[c0 * 32 + l];
    int mydst = g_csr_dst[c0 * 32 + l];

    float m0 = -INFINITY, m1 = -INFINITY;
    int prev = INT_MIN;
    bool at_start = true;
    int prev_dst_stage = -1;
    float2 a2 = make_float2(0.f, 0.f);

    for (int t = c0; t < c1; t++) {
        // ---- stage 32 edges (fp16), unrolled for LDG batching ----
#pragma unroll 8
        for (int rr = 0; rr < 32; rr++) {
            int src = __shfl_sync(0xffffffffu, mysrc, rr);
            int dst = __shfl_sync(0xffffffffu, mydst, rr);
            if (dst != prev_dst_stage) {
                a2 = *(const float2*)(g_A + (long)dst * HID + 2 * l);
                prev_dst_stage = dst;
            }
            float2 q2 = *(const float2*)(g_Q + (long)src * HID + 2 * l);
            float u0 = fmaxf(a2.x + q2.x, 0.f);
            float u1 = fmaxf(a2.y + q2.y, 0.f);
            __half2 hb = __floats2half2_rn(u0, u1);
            uint32_t off = (uint32_t)(rr * 128 + ((l * 4) ^ ((rr & 7) << 4)));
            *(unsigned*)(uw + off) = *reinterpret_cast<unsigned*>(&hb);
        }
        __syncwarp();

        // prefetch next tile's indices
        int nsrc = 0, ndst = 0;
        if (t + 1 < c1) {
            nsrc = g_csr[(t + 1) * 32 + l];
            ndst = g_csr_dst[(t + 1) * 32 + l];
        }

        // ---- MMA: single fp16 term ----
        float d[2][8][4];
#pragma unroll
        for (int rb = 0; rb < 2; rb++)
#pragma unroll
            for (int nb = 0; nb < 8; nb++)
#pragma unroll
                for (int j = 0; j < 4; j++) d[rb][nb][j] = 0.f;

#pragma unroll
        for (int ks = 0; ks < 4; ks++) {
            uint32_t axor = (uint32_t)(((ks * 2 + kgrp) ^ lrow) << 4);
            uint32_t ah[2][4];
            ldsm4(ah[0], a_base0 + axor);
            ldsm4(ah[1], a_base0 + 2048 + axor);
#pragma unroll
            for (int np = 0; np < 4; np++) {
                uint32_t bxor = (uint32_t)(((np * 2 + kgrp) ^ lrow) << 4);
                uint32_t bh[4];
                ldsm4t(bh, w_hi_base + ks * 2048 + bxor);
#pragma unroll
                for (int rb = 0; rb < 2; rb++) {
                    mma16816h(d[rb][2 * np],     ah[rb], bh[0], bh[1]);
                    mma16816h(d[rb][2 * np + 1], ah[rb], bh[2], bh[3]);
                }
            }
        }
        __syncwarp();

        // ---- D -> zbuf (swizzled) ----
#pragma unroll
        for (int rb = 0; rb < 2; rb++) {
#pragma unroll
            for (int nb = 0; nb < 8; nb++) {
                int c0w = nb * 8 + (l & 3) * 2;
                int r0 = rb * 16 + (l >> 2);
                int r1 = r0 + 8;
                *(float2*)&zb[r0 * 64 + (c0w ^ ((r0 & 7) << 3))] =
                    make_float2(d[rb][nb][0], d[rb][nb][1]);
                *(float2*)&zb[r1 * 64 + (c0w ^ ((r1 & 7) << 3))] =
                    make_float2(d[rb][nb][2], d[rb][nb][3]);
            }
        }
        __syncwarp();

        // ---- segmented max; interior plain-store, boundaries atomic ----
        for (int rr = 0; rr < 32; rr++) {
            int dcur = __shfl_sync(0xffffffffu, mydst, rr);
            if (dcur != prev) {
                if (prev != INT_MIN) {
                    flushmax(prev, l, m0, m1, at_start);
                    at_start = false;
                }
                m0 = -INFINITY; m1 = -INFINITY;
                prev = dcur;
            }
            float2 zv = *(const float2*)&zb[rr * 64 + ((2 * l) ^ ((rr & 7) << 3))];
            m0 = fmaxf(m0, zv.x);
            m1 = fmaxf(m1, zv.y);
        }
        __syncwarp();
        mysrc = nsrc;
        mydst = ndst;
    }
    if (prev != INT_MIN) flushmax(prev, l, m0, m1, true);   // chunk-end: boundary
}

// ---------------- last-layer finish: out = (relu(max+b2)+h) @ Wo + bo ----------------
__global__ void __launch_bounds__(256) k_finlast(const float* __restrict__ b2,
                                                 const float* __restrict__ Wo,
                                                 const float* __restrict__ bo,
                                                 float* __restrict__ out) {
    int w = threadIdx.x >> 5, l = threadIdx.x & 31;
    int n = blockIdx.x * 8 + w;
    if (n >= N_NODES) return;
    int deg = g_offsets[n + 1] - g_offsets[n];
    float2 r = *(const float2*)(g_h + (long)n * HID + 2 * l);
    if (deg > 0) {
        unsigned e0 = g_z[(long)n * HID + 2 * l];
        unsigned e1 = g_z[(long)n * HID + 2 * l + 1];
        float2 b2v = *(const float2*)(b2 + 2 * l);
        r.x = fmaxf(decf(e0) + b2v.x, 0.f) + r.x;
        r.y = fmaxf(decf(e1) + b2v.y, 0.f) + r.y;
    }
    float2 wo = *(const float2*)(Wo + 2 * l);
    float s = fmaf(r.x, wo.x, r.y * wo.y);
#pragma unroll
    for (int o = 16; o; o >>= 1) s += __shfl_xor_sync(0xffffffffu, s, o);
    if (l == 0) out[n] = s + bo[0];
}

// ---------------- launch ----------------
extern "C" void kernel_launch(void* const* d_in, const int* in_sizes, int n_in,
                              void* d_out, int out_size) {
    const float* x  = (const float*)d_in[0];
    const int*   ei = (const int*)d_in[1];
    const float* Wp = (const float*)d_in[2];
    const float* bp = (const float*)d_in[3];
    const float* W1 = (const float*)d_in[4];
    const float* b1 = (const float*)d_in[5];
    const float* W2 = (const float*)d_in[6];
    const float* b2 = (const float*)d_in[7];
    const float* Wo = (const float*)d_in[8];
    const float* bo = (const float*)d_in[9];
    float* out = (float*)d_out;

    k_init<<<(N_NODES * HID + 1023) / 1024, 1024>>>(ei, W2);
    k_hist<<<(N_EDGES + 255) / 256, 256>>>(ei);
    k_scan1<<<NSB, SCB>>>();
    k_scan2<<<1, 128>>>();
    k_scan3<<<NSB, SCB>>>();
    k_scatter<<<(N_EDGES + 255) / 256, 256>>>(ei);

    const int NB = (N_NODES + 31) / 32;
    k_proj<<<NB, 256>>>(x, Wp, bp);
    for (int L = 0; L < N_LAYERS; L++) {
        k_AQ<<<NB, 256>>>(W1 + (long)L * 2 * HID * HID, b1 + (long)L * HID,
                          (L > 0) ? (b2 + (long)(L - 1) * HID) : b2, L > 0);
        k_edgemma<<<EMMA_BLOCKS, 128, SMEM_DYN>>>(L);
    }
    k_finlast<<<(N_NODES + 7) / 8, 256>>>(b2 + (long)(N_LAYERS - 1) * HID, Wo, bo, out);
}

// round 15
// speedup vs baseline: 1.0804x; 1.0547x over previous
#include <cuda_runtime.h>
#include <cuda_fp16.h>
#include <cstdint>
#include <climits>

#define N_NODES 50000
#define N_EDGES 800000
#define IN_DIM 128
#define HID 64
#define N_LAYERS 3
#define SCB 512
#define NSB ((N_NODES + SCB - 1) / SCB)

#define NT_W (N_EDGES / 32)          // 25000 warp-tiles, exact
#define EMMA_BLOCKS 592              // 4 blocks/SM x 148
#define TW_TOT (EMMA_BLOCKS * 4)

// ---- dynamic SMEM layout for k_edgemma (40KB, no static shared) ----
#define SM_U    0        // 4 warps x 8KB stripe: U fp16 4KB (union zbuf 32x64 f32 = 8KB)
#define SM_WHI  32768    // W2 fp16 [k][n] swizzled, 8KB
#define SMEM_DYN 40960

// ---------------- scratch ----------------
__device__ float g_h[N_NODES * HID];
__device__ float g_A[N_NODES * HID];
__device__ float g_Q[N_NODES * HID];
__device__ unsigned g_z[N_NODES * HID];     // ordered-encoded max accumulator
__device__ int   g_counts[N_NODES];
__device__ int   g_offsets[N_NODES + 1];
__device__ int   g_cursor[N_NODES];
__device__ int   g_csr[N_EDGES];
__device__ int   g_csr_dst[N_EDGES];
__device__ int   g_bsum[128];
__device__ int   g_bbase[128];
__device__ int   g_is64;
__device__ unsigned g_W2t[N_LAYERS * 64 * 32];   // [L][k][n2] fp16x2

// ---------------- helpers ----------------
__device__ __forceinline__ unsigned long long pk2(float x, float y) {
    unsigned long long r;
    asm("mov.b64 %0, {%1, %2};" : "=l"(r) : "f"(x), "f"(y));
    return r;
}
__device__ __forceinline__ unsigned long long pkdup(float x) {
    unsigned long long r;
    asm("mov.b64 %0, {%1, %1};" : "=l"(r) : "f"(x));
    return r;
}
__device__ __forceinline__ float2 upk2(unsigned long long v) {
    float2 r;
    asm("mov.b64 {%0, %1}, %2;" : "=f"(r.x), "=f"(r.y) : "l"(v));
    return r;
}
__device__ __forceinline__ unsigned long long ffma2(unsigned long long a,
                                                    unsigned long long b,
                                                    unsigned long long c) {
    unsigned long long d;
    asm("fma.rn.f32x2 %0, %1, %2, %3;" : "=l"(d) : "l"(a), "l"(b), "l"(c));
    return d;
}
__device__ __forceinline__ uint32_t smem_u32(const void* p) {
    uint32_t a;
    asm("{ .reg .u64 t; cvta.to.shared.u64 t, %1; cvt.u32.u64 %0, t; }" : "=r"(a) : "l"(p));
    return a;
}
__device__ __forceinline__ unsigned encf(float f) {
    unsigned u = __float_as_uint(f);
    return (u & 0x80000000u) ? ~u : (u | 0x80000000u);
}
__device__ __forceinline__ float decf(unsigned u) {
    return (u & 0x80000000u) ? __uint_as_float(u & 0x7FFFFFFFu) : __uint_as_float(~u);
}

// ---- warp-MMA primitives (base-target legal: sm_80+) ----
__device__ __forceinline__ void ldsm4(uint32_t* r, uint32_t a) {
    asm volatile("ldmatrix.sync.aligned.m8n8.x4.shared.b16 {%0,%1,%2,%3}, [%4];"
        : "=r"(r[0]), "=r"(r[1]), "=r"(r[2]), "=r"(r[3]) : "r"(a));
}
__device__ __forceinline__ void ldsm4t(uint32_t* r, uint32_t a) {
    asm volatile("ldmatrix.sync.aligned.m8n8.x4.trans.shared.b16 {%0,%1,%2,%3}, [%4];"
        : "=r"(r[0]), "=r"(r[1]), "=r"(r[2]), "=r"(r[3]) : "r"(a));
}
__device__ __forceinline__ void mma16816h(float* d, const uint32_t* a, uint32_t b0, uint32_t b1) {
    asm volatile("mma.sync.aligned.m16n8k16.row.col.f32.f16.f16.f32 "
        "{%0,%1,%2,%3}, {%4,%5,%6,%7}, {%8,%9}, {%0,%1,%2,%3};"
        : "+f"(d[0]), "+f"(d[1]), "+f"(d[2]), "+f"(d[3])
        : "r"(a[0]), "r"(a[1]), "r"(a[2]), "r"(a[3]), "r"(b0), "r"(b1));
}

// ---------------- init: zero counts+z, convert W2 to fp16, detect dtype ----------------
__global__ void __launch_bounds__(1024) k_init(const int* __restrict__ ei32,
                                               const float* __restrict__ W2) {
    int i = blockIdx.x * blockDim.x + threadIdx.x;
    if (i < N_NODES * HID) g_z[i] = 0u;
    if (i < N_NODES) g_counts[i] = 0;
    if (i < N_LAYERS * 64 * 32) {
        int L = i / 2048, rem = i % 2048;
        int k = rem >> 5, n2 = rem & 31;
        const float* WL = W2 + L * HID * HID;
        __half2 hb = __floats2half2_rn(WL[k * HID + 2 * n2], WL[k * HID + 2 * n2 + 1]);
        g_W2t[i] = *reinterpret_cast<unsigned*>(&hb);
    }
    if (i == 0) {
        int z = 0;
#pragma unroll
        for (int j = 1; j < 16; j += 2) z |= ei32[j];
        g_is64 = (z == 0) ? 1 : 0;
    }
}

__device__ __forceinline__ int edge_val(const int* __restrict__ e, int i, int is64) {
    return is64 ? e[2 * i] : e[i];
}
__global__ void k_hist(const int* __restrict__ ei32) {
    int e = blockIdx.x * blockDim.x + threadIdx.x;
    if (e < N_EDGES) {
        int d = edge_val(ei32, N_EDGES + e, g_is64);
        if ((unsigned)d < (unsigned)N_NODES) atomicAdd(&g_counts[d], 1);
    }
}
__device__ __forceinline__ int warp_incl_scan(int v, int lane) {
#pragma unroll
    for (int o = 1; o < 32; o <<= 1) {
        int t = __shfl_up_sync(0xffffffffu, v, o);
        if (lane >= o) v += t;
    }
    return v;
}
__global__ void __launch_bounds__(SCB) k_scan1() {
    __shared__ int ws[SCB / 32];
    int tid = threadIdx.x, lane = tid & 31, wid = tid >> 5;
    int i = blockIdx.x * SCB + tid;
    int v = (i < N_NODES) ? g_counts[i] : 0;
#pragma unroll
    for (int o = 16; o; o >>= 1) v += __shfl_xor_sync(0xffffffffu, v, o);
    if (lane == 0) ws[wid] = v;
    __syncthreads();
    if (wid == 0) {
        int s = (lane < SCB / 32) ? ws[lane] : 0;
#pragma unroll
        for (int o = 16; o; o >>= 1) s += __shfl_xor_sync(0xffffffffu, s, o);
        if (lane == 0) g_bsum[blockIdx.x] = s;
    }
}
__global__ void __launch_bounds__(128) k_scan2() {
    __shared__ int wsum[4];
    int tid = threadIdx.x, lane = tid & 31, wid = tid >> 5;
    int c = (tid < NSB) ? g_bsum[tid] : 0;
    int v = warp_incl_scan(c, lane);
    if (lane == 31) wsum[wid] = v;
    __syncthreads();
    int base = 0;
    for (int j = 0; j < wid; j++) base += wsum[j];
    v += base;
    if (tid < NSB) g_bbase[tid] = v - c;
    if (tid == NSB - 1) g_offsets[N_NODES] = v;
}
__global__ void __launch_bounds__(SCB) k_scan3() {
    __shared__ int wsum[SCB / 32];
    int tid = threadIdx.x, lane = tid & 31, wid = tid >> 5;
    int i = blockIdx.x * SCB + tid;
    int c = (i < N_NODES) ? g_counts[i] : 0;
    int v = warp_incl_scan(c, lane);
    if (lane == 31) wsum[wid] = v;
    __syncthreads();
    int base = g_bbase[blockIdx.x];
    for (int j = 0; j < wid; j++) base += wsum[j];
    int excl = base + v - c;
    if (i < N_NODES) {
        g_offsets[i] = excl;
        g_cursor[i]  = excl;
    }
}
__global__ void k_scatter(const int* __restrict__ ei32) {
    int e = blockIdx.x * blockDim.x + threadIdx.x;
    if (e < N_EDGES) {
        int is64 = g_is64;
        int d = edge_val(ei32, N_EDGES + e, is64);
        int s = edge_val(ei32, e, is64);
        if ((unsigned)d < (unsigned)N_NODES && (unsigned)s < (unsigned)N_NODES) {
            int pos = atomicAdd(&g_cursor[d], 1);
            g_csr[pos] = s;
            g_csr_dst[pos] = d;
        }
    }
}

// ---------------- input projection ----------------
__global__ void __launch_bounds__(256) k_proj(const float* __restrict__ x,
                                              const float* __restrict__ Wp,
                                              const float* __restrict__ bp) {
    __shared__ unsigned long long Wsp[IN_DIM * 32];
    __shared__ float xs[32][IN_DIM];
    int tid = threadIdx.x;
    for (int i = tid; i < IN_DIM * 32; i += 256) {
        int k = i >> 5, lc = i & 31;
        Wsp[i] = pk2(Wp[k * HID + 2 * lc], Wp[k * HID + 2 * lc + 1]);
    }
    int w = tid >> 5, l = tid & 31;
    int m0 = w * 4;
#pragma unroll
    for (int sub = 0; sub < 4; sub++) {
        int n = blockIdx.x * 32 + m0 + sub;
        if (n < N_NODES)
            ((float4*)xs[m0 + sub])[l] = ((const float4*)(x + (long)n * IN_DIM))[l];
    }
    __syncthreads();
    unsigned long long bv = pk2(bp[2 * l], bp[2 * l + 1]);
    unsigned long long acc[4] = {bv, bv, bv, bv};
#pragma unroll 4
    for (int k = 0; k < IN_DIM; k++) {
        unsigned long long wv = Wsp[k * 32 + l];
#pragma unroll
        for (int sub = 0; sub < 4; sub++)
            acc[sub] = ffma2(pkdup(xs[m0 + sub][k]), wv, acc[sub]);
    }
#pragma unroll
    for (int sub = 0; sub < 4; sub++) {
        int n = blockIdx.x * 32 + m0 + sub;
        if (n < N_NODES)
            *(float2*)(g_h + (long)n * HID + 2 * l) = upk2(acc[sub]);
    }
}

// ---------------- node GEMMs (fused with previous-layer finish) ----------
__global__ void __launch_bounds__(256) k_AQ(const float* __restrict__ W1,
                                            const float* __restrict__ b1,
                                            const float* __restrict__ b2prev,
                                            int do_fin) {
    __shared__ unsigned long long Wsa[HID * 32];
    __shared__ unsigned long long Wsb[HID * 32];
    __shared__ float hs[32][HID];
    int tid = threadIdx.x;
    for (int i = tid; i < HID * 32; i += 256) {
        int k = i >> 5, lc = i & 31;
        Wsa[i] = pk2(W1[k * HID + 2 * lc], W1[k * HID + 2 * lc + 1]);
        Wsb[i] = pk2(W1[(HID + k) * HID + 2 * lc], W1[(HID + k) * HID + 2 * lc + 1]);
    }
    int w = tid >> 5, l = tid & 31;
    int m0 = w * 4;
#pragma unroll
    for (int sub = 0; sub < 4; sub++) {
        int n = blockIdx.x * 32 + m0 + sub;
        if (n >= N_NODES) continue;
        float2 h2 = *(const float2*)(g_h + (long)n * HID + 2 * l);
        if (do_fin) {
            int deg = g_offsets[n + 1] - g_offsets[n];
            if (deg > 0) {
                unsigned e0 = g_z[(long)n * HID + 2 * l];
                unsigned e1 = g_z[(long)n * HID + 2 * l + 1];
                float2 b2v = *(const float2*)(b2prev + 2 * l);
                h2.x = fmaxf(decf(e0) + b2v.x, 0.f) + h2.x;
                h2.y = fmaxf(decf(e1) + b2v.y, 0.f) + h2.y;
                *(uint2*)(g_z + (long)n * HID + 2 * l) = make_uint2(0u, 0u);
            }
            *(float2*)(g_h + (long)n * HID + 2 * l) = h2;
        }
        ((float2*)hs[m0 + sub])[l] = h2;
    }
    __syncthreads();
    unsigned long long accA[4] = {0ull, 0ull, 0ull, 0ull};
    unsigned long long accQ[4] = {0ull, 0ull, 0ull, 0ull};
#pragma unroll 4
    for (int k = 0; k < HID; k++) {
        unsigned long long wa = Wsa[k * 32 + l];
        unsigned long long wb = Wsb[k * 32 + l];
#pragma unroll
        for (int sub = 0; sub < 4; sub++) {
            unsigned long long hk2 = pkdup(hs[m0 + sub][k]);
            accA[sub] = ffma2(hk2, wa, accA[sub]);
            accQ[sub] = ffma2(hk2, wb, accQ[sub]);
        }
    }
    float2 bv = *(const float2*)(b1 + 2 * l);
#pragma unroll
    for (int sub = 0; sub < 4; sub++) {
        int n = blockIdx.x * 32 + m0 + sub;
        if (n >= N_NODES) continue;
        float2 fA = upk2(accA[sub]);
        float2 fQ = upk2(accQ[sub]);
        float2 A;
        A.x = fA.x - fQ.x + bv.x;
        A.y = fA.y - fQ.y + bv.y;
        *(float2*)(g_A + (long)n * HID + 2 * l) = A;
        *(float2*)(g_Q + (long)n * HID + 2 * l) = fQ;
    }
}

// ---------------- HMMA edge phase ----------------
// Contiguous chunk of 32-edge tiles per warp. U = relu(A[dst]+Q[src]) fp16,
// single-term MMA, segmented max; interior segments plain-stored,
// chunk-boundary segments via encoded atomicMax.
// Staging is chunked 8-wide: reload predicates come from register-resident
// dst values (no memory-carried dependency), loads batch at MLP~16.
__device__ __forceinline__ void flushmax(int node, int l, float m0, float m1, bool boundary) {
    unsigned* p = g_z + (long)node * HID + 2 * l;
    unsigned e0 = encf(m0), e1 = encf(m1);
    if (boundary) {
        atomicMax(p, e0);
        atomicMax(p + 1, e1);
    } else {
        *(uint2*)p = make_uint2(e0, e1);
    }
}

__global__ void __launch_bounds__(128, 4) k_edgemma(int layer) {
    extern __shared__ char sm[];
    uint32_t smb = smem_u32(sm);
    int tid = threadIdx.x, w = tid >> 5, l = tid & 31;

    const unsigned* whg = g_W2t + layer * 2048;
    for (int i = tid; i < 2048; i += 128) {
        int k = i >> 5, n2 = i & 31;
        uint32_t off = (uint32_t)(k * 128 + ((n2 * 4) ^ ((k & 7) << 4)));
        *(unsigned*)(sm + SM_WHI + off) = whg[i];
    }
    __syncthreads();

    char* uw = sm + SM_U + w * 8192;         // U fp16 4KB (zbuf 8KB union)
    uint32_t uw32 = smb + SM_U + w * 8192;
    float* zb = (float*)uw;

    int lrow = l & 7;
    int arow = ((l >> 3) & 1) * 8 + lrow;
    int kgrp = l >> 4;
    uint32_t a_base0 = uw32 + arow * 128;
    uint32_t w_hi_base = smb + SM_WHI + arow * 128;

    int wg = blockIdx.x * 4 + w;
    int c0 = (int)((long)NT_W * wg / TW_TOT);
    int c1 = (int)((long)NT_W * (wg + 1) / TW_TOT);
    if (c0 >= c1) return;

    int mysrc = g_csr[c0 * 32 + l];
    int mydst = g_csr_dst[c0 * 32 + l];

    float m0 = -INFINITY, m1 = -INFINITY;
    int prev = INT_MIN;
    bool at_start = true;
    int prev_dst_stage = -1;
    float2 a2 = make_float2(0.f, 0.f);

    for (int t = c0; t < c1; t++) {
        // ---- stage 32 edges in 4 chunks of 8 (dependency-free load batching) ----
#pragma unroll
        for (int ch = 0; ch < 4; ch++) {
            int dstv[8], srcv[8];
#pragma unroll
            for (int j = 0; j < 8; j++) {
                srcv[j] = __shfl_sync(0xffffffffu, mysrc, ch * 8 + j);
                dstv[j] = __shfl_sync(0xffffffffu, mydst, ch * 8 + j);
            }
            bool rld[8];
            rld[0] = (dstv[0] != prev_dst_stage);
#pragma unroll
            for (int j = 1; j < 8; j++) rld[j] = (dstv[j] != dstv[j - 1]);

            float2 qv[8], av[8];
#pragma unroll
            for (int j = 0; j < 8; j++)
                qv[j] = *(const float2*)(g_Q + (long)srcv[j] * HID + 2 * l);
#pragma unroll
            for (int j = 0; j < 8; j++)
                if (rld[j]) av[j] = *(const float2*)(g_A + (long)dstv[j] * HID + 2 * l);

            if (!rld[0]) av[0] = a2;
#pragma unroll
            for (int j = 1; j < 8; j++)
                if (!rld[j]) av[j] = av[j - 1];
            a2 = av[7];
            prev_dst_stage = dstv[7];

#pragma unroll
            for (int j = 0; j < 8; j++) {
                int rr = ch * 8 + j;
                float u0 = fmaxf(av[j].x + qv[j].x, 0.f);
                float u1 = fmaxf(av[j].y + qv[j].y, 0.f);
                __half2 hb = __floats2half2_rn(u0, u1);
                uint32_t off = (uint32_t)(rr * 128 + ((l * 4) ^ ((rr & 7) << 4)));
                *(unsigned*)(uw + off) = *reinterpret_cast<unsigned*>(&hb);
            }
        }
        __syncwarp();

        // prefetch next tile's indices
        int nsrc = 0, ndst = 0;
        if (t + 1 < c1) {
            nsrc = g_csr[(t + 1) * 32 + l];
            ndst = g_csr_dst[(t + 1) * 32 + l];
        }

        // ---- MMA: single fp16 term ----
        float d[2][8][4];
#pragma unroll
        for (int rb = 0; rb < 2; rb++)
#pragma unroll
            for (int nb = 0; nb < 8; nb++)
#pragma unroll
                for (int j = 0; j < 4; j++) d[rb][nb][j] = 0.f;

#pragma unroll
        for (int ks = 0; ks < 4; ks++) {
            uint32_t axor = (uint32_t)(((ks * 2 + kgrp) ^ lrow) << 4);
            uint32_t ah[2][4];
            ldsm4(ah[0], a_base0 + axor);
            ldsm4(ah[1], a_base0 + 2048 + axor);
#pragma unroll
            for (int np = 0; np < 4; np++) {
                uint32_t bxor = (uint32_t)(((np * 2 + kgrp) ^ lrow) << 4);
                uint32_t bh[4];
                ldsm4t(bh, w_hi_base + ks * 2048 + bxor);
#pragma unroll
                for (int rb = 0; rb < 2; rb++) {
                    mma16816h(d[rb][2 * np],     ah[rb], bh[0], bh[1]);
                    mma16816h(d[rb][2 * np + 1], ah[rb], bh[2], bh[3]);
                }
            }
        }
        __syncwarp();

        // ---- D -> zbuf (swizzled) ----
#pragma unroll
        for (int rb = 0; rb < 2; rb++) {
#pragma unroll
            for (int nb = 0; nb < 8; nb++) {
                int c0w = nb * 8 + (l & 3) * 2;
                int r0 = rb * 16 + (l >> 2);
                int r1 = r0 + 8;
                *(float2*)&zb[r0 * 64 + (c0w ^ ((r0 & 7) << 3))] =
                    make_float2(d[rb][nb][0], d[rb][nb][1]);
                *(float2*)&zb[r1 * 64 + (c0w ^ ((r1 & 7) << 3))] =
                    make_float2(d[rb][nb][2], d[rb][nb][3]);
            }
        }
        __syncwarp();

        // ---- segmented max in 8-chunks (batched LDS) ----
#pragma unroll
        for (int ch = 0; ch < 4; ch++) {
            float2 zv[8];
#pragma unroll
            for (int j = 0; j < 8; j++) {
                int rr = ch * 8 + j;
                zv[j] = *(const float2*)&zb[rr * 64 + ((2 * l) ^ ((rr & 7) << 3))];
            }
#pragma unroll
            for (int j = 0; j < 8; j++) {
                int dcur = __shfl_sync(0xffffffffu, mydst, ch * 8 + j);
                if (dcur != prev) {
                    if (prev != INT_MIN) {
                        flushmax(prev, l, m0, m1, at_start);
                        at_start = false;
                    }
                    m0 = -INFINITY; m1 = -INFINITY;
                    prev = dcur;
                }
                m0 = fmaxf(m0, zv[j].x);
                m1 = fmaxf(m1, zv[j].y);
            }
        }
        __syncwarp();
        mysrc = nsrc;
        mydst = ndst;
    }
    if (prev != INT_MIN) flushmax(prev, l, m0, m1, true);   // chunk-end: boundary
}

// ---------------- last-layer finish: out = (relu(max+b2)+h) @ Wo + bo ----------------
__global__ void __launch_bounds__(256) k_finlast(const float* __restrict__ b2,
                                                 const float* __restrict__ Wo,
                                                 const float* __restrict__ bo,
                                                 float* __restrict__ out) {
    int w = threadIdx.x >> 5, l = threadIdx.x & 31;
    int n = blockIdx.x * 8 + w;
    if (n >= N_NODES) return;
    int deg = g_offsets[n + 1] - g_offsets[n];
    float2 r = *(const float2*)(g_h + (long)n * HID + 2 * l);
    if (deg > 0) {
        unsigned e0 = g_z[(long)n * HID + 2 * l];
        unsigned e1 = g_z[(long)n * HID + 2 * l + 1];
        float2 b2v = *(const float2*)(b2 + 2 * l);
        r.x = fmaxf(decf(e0) + b2v.x, 0.f) + r.x;
        r.y = fmaxf(decf(e1) + b2v.y, 0.f) + r.y;
    }
    float2 wo = *(const float2*)(Wo + 2 * l);
    float s = fmaf(r.x, wo.x, r.y * wo.y);
#pragma unroll
    for (int o = 16; o; o >>= 1) s += __shfl_xor_sync(0xffffffffu, s, o);
    if (l == 0) out[n] = s + bo[0];
}

// ---------------- launch ----------------
extern "C" void kernel_launch(void* const* d_in, const int* in_sizes, int n_in,
                              void* d_out, int out_size) {
    const float* x  = (const float*)d_in[0];
    const int*   ei = (const int*)d_in[1];
    const float* Wp = (const float*)d_in[2];
    const float* bp = (const float*)d_in[3];
    const float* W1 = (const float*)d_in[4];
    const float* b1 = (const float*)d_in[5];
    const float* W2 = (const float*)d_in[6];
    const float* b2 = (const float*)d_in[7];
    const float* Wo = (const float*)d_in[8];
    const float* bo = (const float*)d_in[9];
    float* out = (float*)d_out;

    k_init<<<(N_NODES * HID + 1023) / 1024, 1024>>>(ei, W2);
    k_hist<<<(N_EDGES + 255) / 256, 256>>>(ei);
    k_scan1<<<NSB, SCB>>>();
    k_scan2<<<1, 128>>>();
    k_scan3<<<NSB, SCB>>>();
    k_scatter<<<(N_EDGES + 255) / 256, 256>>>(ei);

    const int NB = (N_NODES + 31) / 32;
    k_proj<<<NB, 256>>>(x, Wp, bp);
    for (int L = 0; L < N_LAYERS; L++) {
        k_AQ<<<NB, 256>>>(W1 + (long)L * 2 * HID * HID, b1 + (long)L * HID,
                          (L > 0) ? (b2 + (long)(L - 1) * HID) : b2, L > 0);
        k_edgemma<<<EMMA_BLOCKS, 128, SMEM_DYN>>>(L);
    }
    k_finlast<<<(N_NODES + 7) / 8, 256>>>(b2 + (long)(N_LAYERS - 1) * HID, Wo, bo, out);
}

// round 16
// speedup vs baseline: 1.1283x; 1.0443x over previous
#include <cuda_runtime.h>
#include <cuda_fp16.h>
#include <cstdint>
#include <climits>

#define N_NODES 50000
#define N_EDGES 800000
#define IN_DIM 128
#define HID 64
#define N_LAYERS 3
#define SCB 512
#define NSB ((N_NODES + SCB - 1) / SCB)

#define NT_W (N_EDGES / 32)          // 25000 warp-tiles, exact
#define EMMA_BLOCKS 592              // 4 blocks/SM x 148
#define TW_TOT (EMMA_BLOCKS * 4)

// ---- dynamic SMEM layout for k_edgemma (40KB, no static shared) ----
#define SM_U    0        // 4 warps x 8KB stripe: U fp16 4KB (union zbuf 32x64 f32 = 8KB)
#define SM_WHI  32768    // W2 fp16 [k][n] swizzled, 8KB
#define SMEM_DYN 40960

// ---------------- scratch ----------------
__device__ float g_h[N_NODES * HID];
__device__ unsigned g_Ah[N_NODES * 32];     // A fp16x2 per lane-col-pair
__device__ unsigned g_Qh[N_NODES * 32];     // Q fp16x2
__device__ unsigned g_z[N_NODES * HID];     // ordered-encoded max accumulator
__device__ int   g_counts[N_NODES];
__device__ int   g_offsets[N_NODES + 1];
__device__ int   g_cursor[N_NODES];
__device__ int2  g_csr2[N_EDGES];           // (src, dst) packed
__device__ int   g_bsum[128];
__device__ int   g_bbase[128];
__device__ int   g_is64;
__device__ unsigned g_W2t[N_LAYERS * 64 * 32];   // [L][k][n2] fp16x2

// ---------------- helpers ----------------
__device__ __forceinline__ unsigned long long pk2(float x, float y) {
    unsigned long long r;
    asm("mov.b64 %0, {%1, %2};" : "=l"(r) : "f"(x), "f"(y));
    return r;
}
__device__ __forceinline__ unsigned long long pkdup(float x) {
    unsigned long long r;
    asm("mov.b64 %0, {%1, %1};" : "=l"(r) : "f"(x));
    return r;
}
__device__ __forceinline__ float2 upk2(unsigned long long v) {
    float2 r;
    asm("mov.b64 {%0, %1}, %2;" : "=f"(r.x), "=f"(r.y) : "l"(v));
    return r;
}
__device__ __forceinline__ unsigned long long ffma2(unsigned long long a,
                                                    unsigned long long b,
                                                    unsigned long long c) {
    unsigned long long d;
    asm("fma.rn.f32x2 %0, %1, %2, %3;" : "=l"(d) : "l"(a), "l"(b), "l"(c));
    return d;
}
__device__ __forceinline__ uint32_t smem_u32(const void* p) {
    uint32_t a;
    asm("{ .reg .u64 t; cvta.to.shared.u64 t, %1; cvt.u32.u64 %0, t; }" : "=r"(a) : "l"(p));
    return a;
}
__device__ __forceinline__ unsigned encf(float f) {
    unsigned u = __float_as_uint(f);
    return (u & 0x80000000u) ? ~u : (u | 0x80000000u);
}
__device__ __forceinline__ float decf(unsigned u) {
    return (u & 0x80000000u) ? __uint_as_float(u & 0x7FFFFFFFu) : __uint_as_float(~u);
}

// ---- warp-MMA primitives (base-target legal: sm_80+) ----
__device__ __forceinline__ void ldsm4(uint32_t* r, uint32_t a) {
    asm volatile("ldmatrix.sync.aligned.m8n8.x4.shared.b16 {%0,%1,%2,%3}, [%4];"
        : "=r"(r[0]), "=r"(r[1]), "=r"(r[2]), "=r"(r[3]) : "r"(a));
}
__device__ __forceinline__ void ldsm4t(uint32_t* r, uint32_t a) {
    asm volatile("ldmatrix.sync.aligned.m8n8.x4.trans.shared.b16 {%0,%1,%2,%3}, [%4];"
        : "=r"(r[0]), "=r"(r[1]), "=r"(r[2]), "=r"(r[3]) : "r"(a));
}
__device__ __forceinline__ void mma16816h(float* d, const uint32_t* a, uint32_t b0, uint32_t b1) {
    asm volatile("mma.sync.aligned.m16n8k16.row.col.f32.f16.f16.f32 "
        "{%0,%1,%2,%3}, {%4,%5,%6,%7}, {%8,%9}, {%0,%1,%2,%3};"
        : "+f"(d[0]), "+f"(d[1]), "+f"(d[2]), "+f"(d[3])
        : "r"(a[0]), "r"(a[1]), "r"(a[2]), "r"(a[3]), "r"(b0), "r"(b1));
}

// ---------------- init: zero counts+z, convert W2 to fp16, detect dtype ----------------
__global__ void __launch_bounds__(1024) k_init(const int* __restrict__ ei32,
                                               const float* __restrict__ W2) {
    int i = blockIdx.x * blockDim.x + threadIdx.x;
    if (i < N_NODES * HID) g_z[i] = 0u;
    if (i < N_NODES) g_counts[i] = 0;
    if (i < N_LAYERS * 64 * 32) {
        int L = i / 2048, rem = i % 2048;
        int k = rem >> 5, n2 = rem & 31;
        const float* WL = W2 + L * HID * HID;
        __half2 hb = __floats2half2_rn(WL[k * HID + 2 * n2], WL[k * HID + 2 * n2 + 1]);
        g_W2t[i] = *reinterpret_cast<unsigned*>(&hb);
    }
    if (i == 0) {
        int z = 0;
#pragma unroll
        for (int j = 1; j < 16; j += 2) z |= ei32[j];
        g_is64 = (z == 0) ? 1 : 0;
    }
}

__device__ __forceinline__ int edge_val(const int* __restrict__ e, int i, int is64) {
    return is64 ? e[2 * i] : e[i];
}
__global__ void k_hist(const int* __restrict__ ei32) {
    int e = blockIdx.x * blockDim.x + threadIdx.x;
    if (e < N_EDGES) {
        int d = edge_val(ei32, N_EDGES + e, g_is64);
        if ((unsigned)d < (unsigned)N_NODES) atomicAdd(&g_counts[d], 1);
    }
}
__device__ __forceinline__ int warp_incl_scan(int v, int lane) {
#pragma unroll
    for (int o = 1; o < 32; o <<= 1) {
        int t = __shfl_up_sync(0xffffffffu, v, o);
        if (lane >= o) v += t;
    }
    return v;
}
__global__ void __launch_bounds__(SCB) k_scan1() {
    __shared__ int ws[SCB / 32];
    int tid = threadIdx.x, lane = tid & 31, wid = tid >> 5;
    int i = blockIdx.x * SCB + tid;
    int v = (i < N_NODES) ? g_counts[i] : 0;
#pragma unroll
    for (int o = 16; o; o >>= 1) v += __shfl_xor_sync(0xffffffffu, v, o);
    if (lane == 0) ws[wid] = v;
    __syncthreads();
    if (wid == 0) {
        int s = (lane < SCB / 32) ? ws[lane] : 0;
#pragma unroll
        for (int o = 16; o; o >>= 1) s += __shfl_xor_sync(0xffffffffu, s, o);
        if (lane == 0) g_bsum[blockIdx.x] = s;
    }
}
__global__ void __launch_bounds__(128) k_scan2() {
    __shared__ int wsum[4];
    int tid = threadIdx.x, lane = tid & 31, wid = tid >> 5;
    int c = (tid < NSB) ? g_bsum[tid] : 0;
    int v = warp_incl_scan(c, lane);
    if (lane == 31) wsum[wid] = v;
    __syncthreads();
    int base = 0;
    for (int j = 0; j < wid; j++) base += wsum[j];
    v += base;
    if (tid < NSB) g_bbase[tid] = v - c;
    if (tid == NSB - 1) g_offsets[N_NODES] = v;
}
__global__ void __launch_bounds__(SCB) k_scan3() {
    __shared__ int wsum[SCB / 32];
    int tid = threadIdx.x, lane = tid & 31, wid = tid >> 5;
    int i = blockIdx.x * SCB + tid;
    int c = (i < N_NODES) ? g_counts[i] : 0;
    int v = warp_incl_scan(c, lane);
    if (lane == 31) wsum[wid] = v;
    __syncthreads();
    int base = g_bbase[blockIdx.x];
    for (int j = 0; j < wid; j++) base += wsum[j];
    int excl = base + v - c;
    if (i < N_NODES) {
        g_offsets[i] = excl;
        g_cursor[i]  = excl;
    }
}
__global__ void k_scatter(const int* __restrict__ ei32) {
    int e = blockIdx.x * blockDim.x + threadIdx.x;
    if (e < N_EDGES) {
        int is64 = g_is64;
        int d = edge_val(ei32, N_EDGES + e, is64);
        int s = edge_val(ei32, e, is64);
        if ((unsigned)d < (unsigned)N_NODES && (unsigned)s < (unsigned)N_NODES) {
            int pos = atomicAdd(&g_cursor[d], 1);
            g_csr2[pos] = make_int2(s, d);
        }
    }
}

// ---------------- input projection ----------------
__global__ void __launch_bounds__(256) k_proj(const float* __restrict__ x,
                                              const float* __restrict__ Wp,
                                              const float* __restrict__ bp) {
    __shared__ unsigned long long Wsp[IN_DIM * 32];
    __shared__ float xs[32][IN_DIM];
    int tid = threadIdx.x;
    for (int i = tid; i < IN_DIM * 32; i += 256) {
        int k = i >> 5, lc = i & 31;
        Wsp[i] = pk2(Wp[k * HID + 2 * lc], Wp[k * HID + 2 * lc + 1]);
    }
    int w = tid >> 5, l = tid & 31;
    int m0 = w * 4;
#pragma unroll
    for (int sub = 0; sub < 4; sub++) {
        int n = blockIdx.x * 32 + m0 + sub;
        if (n < N_NODES)
            ((float4*)xs[m0 + sub])[l] = ((const float4*)(x + (long)n * IN_DIM))[l];
    }
    __syncthreads();
    unsigned long long bv = pk2(bp[2 * l], bp[2 * l + 1]);
    unsigned long long acc[4] = {bv, bv, bv, bv};
#pragma unroll 4
    for (int k = 0; k < IN_DIM; k++) {
        unsigned long long wv = Wsp[k * 32 + l];
#pragma unroll
        for (int sub = 0; sub < 4; sub++)
            acc[sub] = ffma2(pkdup(xs[m0 + sub][k]), wv, acc[sub]);
    }
#pragma unroll
    for (int sub = 0; sub < 4; sub++) {
        int n = blockIdx.x * 32 + m0 + sub;
        if (n < N_NODES)
            *(float2*)(g_h + (long)n * HID + 2 * l) = upk2(acc[sub]);
    }
}

// ---------------- node GEMMs (fused with previous-layer finish); A,Q stored fp16 ------
__global__ void __launch_bounds__(256) k_AQ(const float* __restrict__ W1,
                                            const float* __restrict__ b1,
                                            const float* __restrict__ b2prev,
                                            int do_fin) {
    __shared__ unsigned long long Wsa[HID * 32];
    __shared__ unsigned long long Wsb[HID * 32];
    __shared__ float hs[32][HID];
    int tid = threadIdx.x;
    for (int i = tid; i < HID * 32; i += 256) {
        int k = i >> 5, lc = i & 31;
        Wsa[i] = pk2(W1[k * HID + 2 * lc], W1[k * HID + 2 * lc + 1]);
        Wsb[i] = pk2(W1[(HID + k) * HID + 2 * lc], W1[(HID + k) * HID + 2 * lc + 1]);
    }
    int w = tid >> 5, l = tid & 31;
    int m0 = w * 4;
#pragma unroll
    for (int sub = 0; sub < 4; sub++) {
        int n = blockIdx.x * 32 + m0 + sub;
        if (n >= N_NODES) continue;
        float2 h2 = *(const float2*)(g_h + (long)n * HID + 2 * l);
        if (do_fin) {
            int deg = g_offsets[n + 1] - g_offsets[n];
            if (deg > 0) {
                unsigned e0 = g_z[(long)n * HID + 2 * l];
                unsigned e1 = g_z[(long)n * HID + 2 * l + 1];
                float2 b2v = *(const float2*)(b2prev + 2 * l);
                h2.x = fmaxf(decf(e0) + b2v.x, 0.f) + h2.x;
                h2.y = fmaxf(decf(e1) + b2v.y, 0.f) + h2.y;
                *(uint2*)(g_z + (long)n * HID + 2 * l) = make_uint2(0u, 0u);
            }
            *(float2*)(g_h + (long)n * HID + 2 * l) = h2;
        }
        ((float2*)hs[m0 + sub])[l] = h2;
    }
    __syncthreads();
    unsigned long long accA[4] = {0ull, 0ull, 0ull, 0ull};
    unsigned long long accQ[4] = {0ull, 0ull, 0ull, 0ull};
#pragma unroll 4
    for (int k = 0; k < HID; k++) {
        unsigned long long wa = Wsa[k * 32 + l];
        unsigned long long wb = Wsb[k * 32 + l];
#pragma unroll
        for (int sub = 0; sub < 4; sub++) {
            unsigned long long hk2 = pkdup(hs[m0 + sub][k]);
            accA[sub] = ffma2(hk2, wa, accA[sub]);
            accQ[sub] = ffma2(hk2, wb, accQ[sub]);
        }
    }
    float2 bv = *(const float2*)(b1 + 2 * l);
#pragma unroll
    for (int sub = 0; sub < 4; sub++) {
        int n = blockIdx.x * 32 + m0 + sub;
        if (n >= N_NODES) continue;
        float2 fA = upk2(accA[sub]);
        float2 fQ = upk2(accQ[sub]);
        __half2 ah = __floats2half2_rn(fA.x - fQ.x + bv.x, fA.y - fQ.y + bv.y);
        __half2 qh = __floats2half2_rn(fQ.x, fQ.y);
        g_Ah[(long)n * 32 + l] = *reinterpret_cast<unsigned*>(&ah);
        g_Qh[(long)n * 32 + l] = *reinterpret_cast<unsigned*>(&qh);
    }
}

// ---------------- HMMA edge phase ----------------
// Contiguous chunk of 32-edge tiles per warp. U = hmax2(hadd2(Ah,Qh),0) fp16,
// single-term MMA, segmented max; interior segments plain-stored,
// chunk-boundary segments via encoded atomicMax.
__device__ __forceinline__ void flushmax(int node, int l, float m0, float m1, bool boundary) {
    unsigned* p = g_z + (long)node * HID + 2 * l;
    unsigned e0 = encf(m0), e1 = encf(m1);
    if (boundary) {
        atomicMax(p, e0);
        atomicMax(p + 1, e1);
    } else {
        *(uint2*)p = make_uint2(e0, e1);
    }
}

__global__ void __launch_bounds__(128, 4) k_edgemma(int layer) {
    extern __shared__ char sm[];
    uint32_t smb = smem_u32(sm);
    int tid = threadIdx.x, w = tid >> 5, l = tid & 31;

    const unsigned* whg = g_W2t + layer * 2048;
    for (int i = tid; i < 2048; i += 128) {
        int k = i >> 5, n2 = i & 31;
        uint32_t off = (uint32_t)(k * 128 + ((n2 * 4) ^ ((k & 7) << 4)));
        *(unsigned*)(sm + SM_WHI + off) = whg[i];
    }
    __syncthreads();

    char* uw = sm + SM_U + w * 8192;         // U fp16 4KB (zbuf 8KB union)
    uint32_t uw32 = smb + SM_U + w * 8192;
    float* zb = (float*)uw;

    int lrow = l & 7;
    int arow = ((l >> 3) & 1) * 8 + lrow;
    int kgrp = l >> 4;
    uint32_t a_base0 = uw32 + arow * 128;
    uint32_t w_hi_base = smb + SM_WHI + arow * 128;

    int wg = blockIdx.x * 4 + w;
    int c0 = (int)((long)NT_W * wg / TW_TOT);
    int c1 = (int)((long)NT_W * (wg + 1) / TW_TOT);
    if (c0 >= c1) return;

    int2 myed = g_csr2[c0 * 32 + l];

    const __half2 z2 = __float2half2_rn(0.f);
    float m0 = -INFINITY, m1 = -INFINITY;
    int prev = INT_MIN;
    bool at_start = true;
    int prev_dst_stage = -1;
    unsigned a2 = 0u;

    for (int t = c0; t < c1; t++) {
        // ---- stage 32 edges in 4 chunks of 8 (dependency-free fp16 load batching) ----
#pragma unroll
        for (int ch = 0; ch < 4; ch++) {
            int dstv[8], srcv[8];
#pragma unroll
            for (int j = 0; j < 8; j++) {
                srcv[j] = __shfl_sync(0xffffffffu, myed.x, ch * 8 + j);
                dstv[j] = __shfl_sync(0xffffffffu, myed.y, ch * 8 + j);
            }
            bool rld[8];
            rld[0] = (dstv[0] != prev_dst_stage);
#pragma unroll
            for (int j = 1; j < 8; j++) rld[j] = (dstv[j] != dstv[j - 1]);

            unsigned qv[8], av[8];
#pragma unroll
            for (int j = 0; j < 8; j++)
                qv[j] = g_Qh[(long)srcv[j] * 32 + l];
#pragma unroll
            for (int j = 0; j < 8; j++)
                if (rld[j]) av[j] = g_Ah[(long)dstv[j] * 32 + l];

            if (!rld[0]) av[0] = a2;
#pragma unroll
            for (int j = 1; j < 8; j++)
                if (!rld[j]) av[j] = av[j - 1];
            a2 = av[7];
            prev_dst_stage = dstv[7];

#pragma unroll
            for (int j = 0; j < 8; j++) {
                int rr = ch * 8 + j;
                __half2 u = __hmax2(__hadd2(*reinterpret_cast<__half2*>(&av[j]),
                                            *reinterpret_cast<__half2*>(&qv[j])), z2);
                uint32_t off = (uint32_t)(rr * 128 + ((l * 4) ^ ((rr & 7) << 4)));
                *(unsigned*)(uw + off) = *reinterpret_cast<unsigned*>(&u);
            }
        }
        __syncwarp();

        // prefetch next tile's indices
        int2 ned = make_int2(0, 0);
        if (t + 1 < c1) ned = g_csr2[(t + 1) * 32 + l];

        // ---- MMA: single fp16 term ----
        float d[2][8][4];
#pragma unroll
        for (int rb = 0; rb < 2; rb++)
#pragma unroll
            for (int nb = 0; nb < 8; nb++)
#pragma unroll
                for (int j = 0; j < 4; j++) d[rb][nb][j] = 0.f;

#pragma unroll
        for (int ks = 0; ks < 4; ks++) {
            uint32_t axor = (uint32_t)(((ks * 2 + kgrp) ^ lrow) << 4);
            uint32_t ah[2][4];
            ldsm4(ah[0], a_base0 + axor);
            ldsm4(ah[1], a_base0 + 2048 + axor);
#pragma unroll
            for (int np = 0; np < 4; np++) {
                uint32_t bxor = (uint32_t)(((np * 2 + kgrp) ^ lrow) << 4);
                uint32_t bh[4];
                ldsm4t(bh, w_hi_base + ks * 2048 + bxor);
#pragma unroll
                for (int rb = 0; rb < 2; rb++) {
                    mma16816h(d[rb][2 * np],     ah[rb], bh[0], bh[1]);
                    mma16816h(d[rb][2 * np + 1], ah[rb], bh[2], bh[3]);
                }
            }
        }
        __syncwarp();

        // ---- D -> zbuf (swizzled) ----
#pragma unroll
        for (int rb = 0; rb < 2; rb++) {
#pragma unroll
            for (int nb = 0; nb < 8; nb++) {
                int c0w = nb * 8 + (l & 3) * 2;
                int r0 = rb * 16 + (l >> 2);
                int r1 = r0 + 8;
                *(float2*)&zb[r0 * 64 + (c0w ^ ((r0 & 7) << 3))] =
                    make_float2(d[rb][nb][0], d[rb][nb][1]);
                *(float2*)&zb[r1 * 64 + (c0w ^ ((r1 & 7) << 3))] =
                    make_float2(d[rb][nb][2], d[rb][nb][3]);
            }
        }
        __syncwarp();

        // ---- segmented max in 8-chunks (batched LDS) ----
#pragma unroll
        for (int ch = 0; ch < 4; ch++) {
            float2 zv[8];
#pragma unroll
            for (int j = 0; j < 8; j++) {
                int rr = ch * 8 + j;
                zv[j] = *(const float2*)&zb[rr * 64 + ((2 * l) ^ ((rr & 7) << 3))];
            }
#pragma unroll
            for (int j = 0; j < 8; j++) {
                int dcur = __shfl_sync(0xffffffffu, myed.y, ch * 8 + j);
                if (dcur != prev) {
                    if (prev != INT_MIN) {
                        flushmax(prev, l, m0, m1, at_start);
                        at_start = false;
                    }
                    m0 = -INFINITY; m1 = -INFINITY;
                    prev = dcur;
                }
                m0 = fmaxf(m0, zv[j].x);
                m1 = fmaxf(m1, zv[j].y);
            }
        }
        __syncwarp();
        myed = ned;
    }
    if (prev != INT_MIN) flushmax(prev, l, m0, m1, true);   // chunk-end: boundary
}

// ---------------- last-layer finish: out = (relu(max+b2)+h) @ Wo + bo ----------------
__global__ void __launch_bounds__(256) k_finlast(const float* __restrict__ b2,
                                                 const float* __restrict__ Wo,
                                                 const float* __restrict__ bo,
                                                 float* __restrict__ out) {
    int w = threadIdx.x >> 5, l = threadIdx.x & 31;
    int n = blockIdx.x * 8 + w;
    if (n >= N_NODES) return;
    int deg = g_offsets[n + 1] - g_offsets[n];
    float2 r = *(const float2*)(g_h + (long)n * HID + 2 * l);
    if (deg > 0) {
        unsigned e0 = g_z[(long)n * HID + 2 * l];
        unsigned e1 = g_z[(long)n * HID + 2 * l + 1];
        float2 b2v = *(const float2*)(b2 + 2 * l);
        r.x = fmaxf(decf(e0) + b2v.x, 0.f) + r.x;
        r.y = fmaxf(decf(e1) + b2v.y, 0.f) + r.y;
    }
    float2 wo = *(const float2*)(Wo + 2 * l);
    float s = fmaf(r.x, wo.x, r.y * wo.y);
#pragma unroll
    for (int o = 16; o; o >>= 1) s += __shfl_xor_sync(0xffffffffu, s, o);
    if (l == 0) out[n] = s + bo[0];
}

// ---------------- launch ----------------
extern "C" void kernel_launch(void* const* d_in, const int* in_sizes, int n_in,
                              void* d_out, int out_size) {
    const float* x  = (const float*)d_in[0];
    const int*   ei = (const int*)d_in[1];
    const float* Wp = (const float*)d_in[2];
    const float* bp = (const float*)d_in[3];
    const float* W1 = (const float*)d_in[4];
    const float* b1 = (const float*)d_in[5];
    const float* W2 = (const float*)d_in[6];
    const float* b2 = (const float*)d_in[7];
    const float* Wo = (const float*)d_in[8];
    const float* bo = (const float*)d_in[9];
    float* out = (float*)d_out;

    k_init<<<(N_NODES * HID + 1023) / 1024, 1024>>>(ei, W2);
    k_hist<<<(N_EDGES + 255) / 256, 256>>>(ei);
    k_scan1<<<NSB, SCB>>>();
    k_scan2<<<1, 128>>>();
    k_scan3<<<NSB, SCB>>>();
    k_scatter<<<(N_EDGES + 255) / 256, 256>>>(ei);

    const int NB = (N_NODES + 31) / 32;
    k_proj<<<NB, 256>>>(x, Wp, bp);
    for (int L = 0; L < N_LAYERS; L++) {
        k_AQ<<<NB, 256>>>(W1 + (long)L * 2 * HID * HID, b1 + (long)L * HID,
                          (L > 0) ? (b2 + (long)(L - 1) * HID) : b2, L > 0);
        k_edgemma<<<EMMA_BLOCKS, 128, SMEM_DYN>>>(L);
    }
    k_finlast<<<(N_NODES + 7) / 8, 256>>>(b2 + (long)(N_LAYERS - 1) * HID, Wo, bo, out);
}